// round 9
// baseline (speedup 1.0000x reference)
#include <cuda_runtime.h>
#include <math.h>

#define NB 512
#define DMODEL 2048
#define NH 8
#define DMEM 128
#define NM 512
#define KPROJ_N 1024     // H*DMEM
#define VPROJ_N 2048     // 2*H*DMEM
#define MEM_ELEMS (NB*NM*DMEM)

// Scratch (device globals: no allocation allowed)
__device__ float g_ak[NB * KPROJ_N];
__device__ float g_v [NB * VPROJ_N];
__device__ float g_aq[NM * DMEM];
__device__ float g_si[NM * DMEM];
__device__ float g_S [NB * NM * NH];

__device__ __forceinline__ float actf(float x) {
    return x > 0.f ? x + 1.f : __expf(x);   // elu(x)+1
}
__device__ __forceinline__ float sigm(float x) {
    return 1.f / (1.f + __expf(-x));
}
__device__ __forceinline__ unsigned f2tf32(float x) {
    unsigned r; asm("cvt.rna.tf32.f32 %0, %1;" : "=r"(r) : "f"(x)); return r;
}
__device__ __forceinline__ float f2tf32f(float x) {
    return __uint_as_float(f2tf32(x));
}
__device__ __forceinline__ void cp16(void* s, const void* g) {
    unsigned sa = (unsigned)__cvta_generic_to_shared(s);
    asm volatile("cp.async.cg.shared.global [%0], [%1], 16;\n" :: "r"(sa), "l"(g));
}
__device__ __forceinline__ void cp4(void* s, const void* g) {
    unsigned sa = (unsigned)__cvta_generic_to_shared(s);
    asm volatile("cp.async.ca.shared.global [%0], [%1], 4;\n" :: "r"(sa), "l"(g));
}
#define CP_COMMIT() asm volatile("cp.async.commit_group;\n" ::: "memory")
#define CP_WAIT(n)  asm volatile("cp.async.wait_group %0;\n" :: "n"(n) : "memory")

// ---------------------------------------------------------------------------
// K0: aq = act(addresses), si = sigmoid(interpolation_logits)
// ---------------------------------------------------------------------------
__global__ void prep_kernel(const float* __restrict__ addresses,
                            const float* __restrict__ interp) {
    int i = blockIdx.x * blockDim.x + threadIdx.x;
    if (i < NM * DMEM) {
        g_aq[i] = actf(addresses[i]);
        g_si[i] = sigm(interp[i]);
    }
}

// ---------------------------------------------------------------------------
// K1: fused projection GEMMs via mma.sync tf32 (m16n8k8)
//   BM=64 BN=64 BK=32, 256 threads (8 warps, 2x4), warp tile 32x16.
//   Fragment-ordered smem: compute loop reads LDS.128 (A) / LDS.64 (B),
//   conflict-free (R8 loop did 48 scalar LDS.32 per warp per kt).
// ---------------------------------------------------------------------------
#define BM 64
#define BN 64
#define BK 32

// A fragment index: element (m,k) of the 64x32 tile, fragment order
__device__ __forceinline__ int fragA_idx(int m, int k) {
    return (((m >> 4) * 4 + (k >> 3)) << 7)          // 16x8 block, 128 floats each
         + ((((m & 7) << 2) | (k & 3)) << 2)         // lane*4
         + ((((k >> 2) & 1) << 1) | ((m >> 3) & 1)); // reg
}
// B fragment index: element (k,n) of the 32x64 tile
__device__ __forceinline__ int fragB_idx(int k, int n) {
    return (((n >> 3) * 4 + (k >> 3)) << 6)          // 8(n)x8(k) block, 64 floats
         + ((((n & 7) << 2) | (k & 3)) << 1)         // lane*2
         + ((k >> 2) & 1);                           // reg
}

__global__ __launch_bounds__(256) void proj_mma_kernel(
    const float* __restrict__ key, const float* __restrict__ values,
    const float* __restrict__ W_key, const float* __restrict__ b_key,
    const float* __restrict__ W_val, const float* __restrict__ b_val)
{
    const float *A, *W, *bias;
    float* C;
    int N, doact;
    int bx = blockIdx.x;
    if (bx < KPROJ_N / BN) { A = key;    W = W_key; bias = b_key; C = g_ak; N = KPROJ_N; doact = 1; }
    else { bx -= KPROJ_N / BN; A = values; W = W_val; bias = b_val; C = g_v; N = VPROJ_N; doact = 0; }

    __shared__ float As[2][2048];   // fragment-ordered A tile (64x32)
    __shared__ float Bs[2][2048];   // fragment-ordered B tile (32x64)

    int t = threadIdx.x;
    int lane = t & 31;
    int warp = t >> 5;
    int g  = lane >> 2;
    int tg = lane & 3;
    int wm = (warp & 1) * 32;  // warp m-offset (wmb = wm/16)
    int wn = (warp >> 1) * 16; // warp n-offset (wnb = wn/8)
    int wmb = (warp & 1) * 2;
    int wnb = (warp >> 1) * 2;
    int bm0 = blockIdx.y * BM;
    int bn0 = bx * BN;

    float acc[2][2][4];
    #pragma unroll
    for (int i = 0; i < 2; i++)
        #pragma unroll
        for (int j = 0; j < 2; j++)
            #pragma unroll
            for (int r = 0; r < 4; r++) acc[i][j][r] = 0.f;

    int ar0 = t >> 3,        ac0 = (t & 7) * 4;     // A rows 0..31, k cols
    int ar1 = ar0 + 32;
    int bk0 = t >> 4,        bn4 = (t & 15) * 4;    // B k 0..15, n cols

    // precompute fragment store offsets (depend only on t)
    int aoff0[4], aoff1[4], boff0[4], boff1[4];
    #pragma unroll
    for (int j = 0; j < 4; j++) {
        aoff0[j] = fragA_idx(ar0, ac0 + j);
        aoff1[j] = fragA_idx(ar1, ac0 + j);
        boff0[j] = fragB_idx(bk0,      bn4 + j);
        boff1[j] = fragB_idx(bk0 + 16, bn4 + j);
    }

    const float* Ab = A + (size_t)bm0 * DMODEL;

    float4 aR0, aR1, bR0, bR1;

    // prologue: tile 0
    aR0 = *(const float4*)(Ab + (size_t)ar0 * DMODEL + ac0);
    aR1 = *(const float4*)(Ab + (size_t)ar1 * DMODEL + ac0);
    bR0 = *(const float4*)(W + (size_t)bk0 * N + bn0 + bn4);
    bR1 = *(const float4*)(W + (size_t)(bk0 + 16) * N + bn0 + bn4);
    {
        float* Asb = As[0]; float* Bsb = Bs[0];
        float av0[4] = {aR0.x, aR0.y, aR0.z, aR0.w};
        float av1[4] = {aR1.x, aR1.y, aR1.z, aR1.w};
        float bv0[4] = {bR0.x, bR0.y, bR0.z, bR0.w};
        float bv1[4] = {bR1.x, bR1.y, bR1.z, bR1.w};
        #pragma unroll
        for (int j = 0; j < 4; j++) {
            Asb[aoff0[j]] = f2tf32f(av0[j]);
            Asb[aoff1[j]] = f2tf32f(av1[j]);
            Bsb[boff0[j]] = f2tf32f(bv0[j]);
            Bsb[boff1[j]] = f2tf32f(bv1[j]);
        }
    }
    __syncthreads();

    const int NKT = DMODEL / BK;   // 64
    int buf = 0;
    for (int kt = 0; kt < NKT; kt++) {
        if (kt + 1 < NKT) {
            int k0 = (kt + 1) * BK;
            aR0 = *(const float4*)(Ab + (size_t)ar0 * DMODEL + k0 + ac0);
            aR1 = *(const float4*)(Ab + (size_t)ar1 * DMODEL + k0 + ac0);
            bR0 = *(const float4*)(W + (size_t)(k0 + bk0) * N + bn0 + bn4);
            bR1 = *(const float4*)(W + (size_t)(k0 + bk0 + 16) * N + bn0 + bn4);
        }

        const float4* Af = (const float4*)As[buf];
        const float2* Bf = (const float2*)Bs[buf];
        #pragma unroll
        for (int ks = 0; ks < 4; ks++) {
            float4 a[2]; float2 b[2];
            #pragma unroll
            for (int ms = 0; ms < 2; ms++)
                a[ms] = Af[((wmb + ms) * 4 + ks) * 32 + lane];
            #pragma unroll
            for (int ns = 0; ns < 2; ns++)
                b[ns] = Bf[((wnb + ns) * 4 + ks) * 32 + lane];
            #pragma unroll
            for (int ms = 0; ms < 2; ms++)
                #pragma unroll
                for (int ns = 0; ns < 2; ns++) {
                    asm volatile(
                        "mma.sync.aligned.m16n8k8.row.col.f32.tf32.tf32.f32 "
                        "{%0,%1,%2,%3}, {%4,%5,%6,%7}, {%8,%9}, {%0,%1,%2,%3};\n"
                        : "+f"(acc[ms][ns][0]), "+f"(acc[ms][ns][1]),
                          "+f"(acc[ms][ns][2]), "+f"(acc[ms][ns][3])
                        : "r"(__float_as_uint(a[ms].x)), "r"(__float_as_uint(a[ms].y)),
                          "r"(__float_as_uint(a[ms].z)), "r"(__float_as_uint(a[ms].w)),
                          "r"(__float_as_uint(b[ns].x)), "r"(__float_as_uint(b[ns].y)));
                }
        }

        if (kt + 1 < NKT) {
            int nb = buf ^ 1;
            float* Asb = As[nb]; float* Bsb = Bs[nb];
            float av0[4] = {aR0.x, aR0.y, aR0.z, aR0.w};
            float av1[4] = {aR1.x, aR1.y, aR1.z, aR1.w};
            float bv0[4] = {bR0.x, bR0.y, bR0.z, bR0.w};
            float bv1[4] = {bR1.x, bR1.y, bR1.z, bR1.w};
            #pragma unroll
            for (int j = 0; j < 4; j++) {
                Asb[aoff0[j]] = f2tf32f(av0[j]);
                Asb[aoff1[j]] = f2tf32f(av1[j]);
                Bsb[boff0[j]] = f2tf32f(bv0[j]);
                Bsb[boff1[j]] = f2tf32f(bv1[j]);
            }
            __syncthreads();
            buf = nb;
        }
    }

    #pragma unroll
    for (int ms = 0; ms < 2; ms++) {
        int row0 = bm0 + wm + ms * 16 + g;
        #pragma unroll
        for (int ns = 0; ns < 2; ns++) {
            int col = bn0 + wn + ns * 8 + 2 * tg;
            float b0 = bias[col], b1 = bias[col + 1];
            float o0 = acc[ms][ns][0] + b0;
            float o1 = acc[ms][ns][1] + b1;
            float o2 = acc[ms][ns][2] + b0;
            float o3 = acc[ms][ns][3] + b1;
            if (doact) { o0 = actf(o0); o1 = actf(o1); o2 = actf(o2); o3 = actf(o3); }
            float2 lo = {o0, o1}, hi = {o2, o3};
            *(float2*)(C + (size_t)row0 * N + col)       = lo;
            *(float2*)(C + (size_t)(row0 + 8) * N + col) = hi;
        }
    }
}

// ---------------------------------------------------------------------------
// K2: S[b,m,h] = sum_d aq[m,d] * ak[b,h,d]
// ---------------------------------------------------------------------------
__global__ __launch_bounds__(256) void s_kernel() {
    int b  = blockIdx.y;
    int m0 = blockIdx.x * 32;
    __shared__ float ak_s[8][132];
    __shared__ float aq_s[32][132];
    int t = threadIdx.x;
    {
        int h = t >> 5, d4 = (t & 31) * 4;
        float4 v = *(const float4*)&g_ak[b * KPROJ_N + h * DMEM + d4];
        *(float4*)&ak_s[h][d4] = v;
    }
    #pragma unroll
    for (int i = 0; i < 4; i++) {
        int idx = t + i * 256;
        int ml = idx >> 5, d4 = (idx & 31) * 4;
        float4 v = *(const float4*)&g_aq[(m0 + ml) * DMEM + d4];
        *(float4*)&aq_s[ml][d4] = v;
    }
    __syncthreads();
    int ml = t >> 3, h = t & 7;
    float s = 0.f;
    #pragma unroll
    for (int d4 = 0; d4 < 32; d4++) {
        float4 a = *(const float4*)&aq_s[ml][d4 * 4];
        float4 k = *(const float4*)&ak_s[h][d4 * 4];
        s += a.x * k.x + a.y * k.y + a.z * k.z + a.w * k.w;
    }
    g_S[(b * NM + m0 + ml) * NH + h] = s;
}

// ---------------------------------------------------------------------------
// K3: epilogue. h-loop outermost, 4 m-rows/thread. Streaming inputs come in
// via cp.async into smem (zero register cost MLP; R8 showed register-held
// MLP collapsed occupancy to 22%). si held in regs (16) to stay under 48KB.
// ---------------------------------------------------------------------------
__global__ __launch_bounds__(256) void epilogue_kernel(
    const float* __restrict__ memories, const float* __restrict__ write_mass,
    const unsigned char* __restrict__ batch_mask, float* __restrict__ out)
{
    int b  = blockIdx.y;
    int m0 = blockIdx.x * 32;
    __shared__ float4 v_s[NH * 64];      // 8 KB  v[h][e4]
    __shared__ float  S_s[256];          // 1 KB  S[row*8+h]
    __shared__ float4 mem_s[32 * 32];    // 16 KB [row][d4]
    __shared__ float4 wm_s [32 * 32];    // 16 KB
    int t = threadIdx.x;
    int ml = t >> 5;
    int d4 = t & 31;
    int r0 = ml * 4;

    // si held in regs (issued first, consumed last)
    float4 si4[4];
    #pragma unroll
    for (int i = 0; i < 4; i++)
        si4[i] = *(const float4*)&g_si[(m0 + r0 + i) * DMEM + d4 * 4];
    unsigned char msk = batch_mask[b];

    // group A: v + S (needed by compute phase)
    const float4* gv = (const float4*)(g_v + (size_t)b * VPROJ_N);
    cp16(&v_s[t],       &gv[t]);
    cp16(&v_s[t + 256], &gv[t + 256]);
    cp4(&S_s[t], &g_S[((size_t)b * NM + m0) * NH + t]);
    CP_COMMIT();

    // group B: memories + write_mass (needed at tail)
    #pragma unroll
    for (int i = 0; i < 4; i++) {
        int row = r0 + i;
        size_t base = ((size_t)b * NM + m0 + row) * DMEM + d4 * 4;
        cp16(&mem_s[row * 32 + d4], &memories[base]);
        cp16(&wm_s [row * 32 + d4], &write_mass[base]);
    }
    CP_COMMIT();

    CP_WAIT(1);          // group A done
    __syncthreads();

    float4 aU[4], aL[4];
    float dn[4];
    #pragma unroll
    for (int i = 0; i < 4; i++) {
        aU[i] = make_float4(0.f, 0.f, 0.f, 0.f);
        aL[i] = make_float4(0.f, 0.f, 0.f, 0.f);
        dn[i] = 1e-5f;
    }

    #pragma unroll
    for (int h = 0; h < 8; h++) {
        float4 vu = v_s[h * 64 + d4];
        float4 vl = v_s[h * 64 + 32 + d4];
        #pragma unroll
        for (int i = 0; i < 4; i++) {
            float s = S_s[(r0 + i) * 8 + h];   // warp-uniform broadcast
            dn[i] += s;
            aU[i].x = fmaf(s, vu.x, aU[i].x); aU[i].y = fmaf(s, vu.y, aU[i].y);
            aU[i].z = fmaf(s, vu.z, aU[i].z); aU[i].w = fmaf(s, vu.w, aU[i].w);
            aL[i].x = fmaf(s, vl.x, aL[i].x); aL[i].y = fmaf(s, vl.y, aL[i].y);
            aL[i].z = fmaf(s, vl.z, aL[i].z); aL[i].w = fmaf(s, vl.w, aL[i].w);
        }
    }

    CP_WAIT(0);          // group B done
    __syncthreads();

    #pragma unroll
    for (int i = 0; i < 4; i++) {
        int row = r0 + i;
        size_t base = ((size_t)b * NM + m0 + row) * DMEM + d4 * 4;
        float4 mem = mem_s[row * 32 + d4];
        float4 wm4 = wm_s [row * 32 + d4];

        float rd = __fdividef(1.f, dn[i]);
        float4 wf;
        wf.x = 0.7f * sigm(aL[i].x * rd) * si4[i].x;
        wf.y = 0.7f * sigm(aL[i].y * rd) * si4[i].y;
        wf.z = 0.7f * sigm(aL[i].z * rd) * si4[i].z;
        wf.w = 0.7f * sigm(aL[i].w * rd) * si4[i].w;

        float4 om, oa;
        if (msk) {
            om = mem; oa = wm4;
        } else {
            om.x = mem.x + wf.x * (aU[i].x * rd - mem.x);
            om.y = mem.y + wf.y * (aU[i].y * rd - mem.y);
            om.z = mem.z + wf.z * (aU[i].z * rd - mem.z);
            om.w = mem.w + wf.w * (aU[i].w * rd - mem.w);
            oa.x = wm4.x + wf.x; oa.y = wm4.y + wf.y;
            oa.z = wm4.z + wf.z; oa.w = wm4.w + wf.w;
        }
        *(float4*)&out[base] = om;
        *(float4*)&out[MEM_ELEMS + base] = oa;
    }
}

// ---------------------------------------------------------------------------
extern "C" void kernel_launch(void* const* d_in, const int* in_sizes, int n_in,
                              void* d_out, int out_size) {
    const float* key        = (const float*)d_in[0];
    const float* values     = (const float*)d_in[1];
    const float* memories   = (const float*)d_in[2];
    const float* write_mass = (const float*)d_in[3];
    const unsigned char* batch_mask = (const unsigned char*)d_in[4];
    const float* W_key      = (const float*)d_in[5];
    const float* b_key      = (const float*)d_in[6];
    const float* W_val      = (const float*)d_in[7];
    const float* b_val      = (const float*)d_in[8];
    const float* addresses  = (const float*)d_in[9];
    const float* interp     = (const float*)d_in[10];
    float* out = (float*)d_out;

    prep_kernel<<<256, 256>>>(addresses, interp);
    proj_mma_kernel<<<dim3((KPROJ_N + VPROJ_N) / BN, NB / BM), 256>>>(
        key, values, W_key, b_key, W_val, b_val);
    s_kernel<<<dim3(NM / 32, NB), 256>>>();
    epilogue_kernel<<<dim3(NM / 32, NB), 256>>>(memories, write_mass, batch_mask, out);
}

// round 10
// speedup vs baseline: 1.6501x; 1.6501x over previous
#include <cuda_runtime.h>
#include <math.h>

#define NB 512
#define DMODEL 2048
#define NH 8
#define DMEM 128
#define NM 512
#define KPROJ_N 1024     // H*DMEM
#define VPROJ_N 2048     // 2*H*DMEM
#define MEM_ELEMS (NB*NM*DMEM)

// Scratch (device globals: no allocation allowed)
__device__ float g_ak[NB * KPROJ_N];
__device__ float g_v [NB * VPROJ_N];
__device__ float g_aq[NM * DMEM];
__device__ float g_si[NM * DMEM];
__device__ float g_S [NB * NM * NH];

__device__ __forceinline__ float actf(float x) {
    return x > 0.f ? x + 1.f : __expf(x);   // elu(x)+1
}
__device__ __forceinline__ float sigm(float x) {
    return 1.f / (1.f + __expf(-x));
}
__device__ __forceinline__ void cp16(void* s, const void* g) {
    unsigned sa = (unsigned)__cvta_generic_to_shared(s);
    asm volatile("cp.async.cg.shared.global [%0], [%1], 16;\n" :: "r"(sa), "l"(g));
}
__device__ __forceinline__ void cp4(void* s, const void* g) {
    unsigned sa = (unsigned)__cvta_generic_to_shared(s);
    asm volatile("cp.async.ca.shared.global [%0], [%1], 4;\n" :: "r"(sa), "l"(g));
}
#define CP_COMMIT() asm volatile("cp.async.commit_group;\n" ::: "memory")
#define CP_WAIT(n)  asm volatile("cp.async.wait_group %0;\n" :: "n"(n) : "memory")

// ---------------------------------------------------------------------------
// K0: aq = act(addresses), si = sigmoid(interpolation_logits)
// ---------------------------------------------------------------------------
__global__ void prep_kernel(const float* __restrict__ addresses,
                            const float* __restrict__ interp) {
    int i = blockIdx.x * blockDim.x + threadIdx.x;
    if (i < NM * DMEM) {
        g_aq[i] = actf(addresses[i]);
        g_si[i] = sigm(interp[i]);
    }
}

// ---------------------------------------------------------------------------
// K1: fused projection GEMMs via mma.sync tf32 (m16n8k8)
//   BM=64 BN=64 BK=32, 256 threads (8 warps, 2x4), warp tile 32x16.
//   R8's padded row-major smem layout (R9 fragment layout regressed: STS
//   scatter conflicts). NEW: global->smem via cp.async, no register staging,
//   no cvt (tf32 MMA truncates raw fp32 bits; rel-err budget is ample).
// ---------------------------------------------------------------------------
#define BM 64
#define BN 64
#define BK 32
#define PADA 36
#define PADB 72

__global__ __launch_bounds__(256) void proj_mma_kernel(
    const float* __restrict__ key, const float* __restrict__ values,
    const float* __restrict__ W_key, const float* __restrict__ b_key,
    const float* __restrict__ W_val, const float* __restrict__ b_val)
{
    const float *A, *W, *bias;
    float* C;
    int N, doact;
    int bx = blockIdx.x;
    if (bx < KPROJ_N / BN) { A = key;    W = W_key; bias = b_key; C = g_ak; N = KPROJ_N; doact = 1; }
    else { bx -= KPROJ_N / BN; A = values; W = W_val; bias = b_val; C = g_v; N = VPROJ_N; doact = 0; }

    __shared__ float As[2][BM][PADA];   // [stage][m][k]
    __shared__ float Bs[2][BK][PADB];   // [stage][k][n]

    int t = threadIdx.x;
    int lane = t & 31;
    int warp = t >> 5;
    int g  = lane >> 2;       // group id 0..7
    int tg = lane & 3;        // thread-in-group 0..3
    int wm = (warp & 1) * 32; // warp m-offset
    int wn = (warp >> 1) * 16;// warp n-offset
    int bm0 = blockIdx.y * BM;
    int bn0 = bx * BN;

    float acc[2][2][4];
    #pragma unroll
    for (int i = 0; i < 2; i++)
        #pragma unroll
        for (int j = 0; j < 2; j++)
            #pragma unroll
            for (int r = 0; r < 4; r++) acc[i][j][r] = 0.f;

    int ar0 = t >> 3,        ac0 = (t & 7) * 4;     // A rows 0..31
    int ar1 = ar0 + 32;                              // A rows 32..63
    int bk0 = t >> 4,        bn4 = (t & 15) * 4;    // B k 0..15

    const float* Ab = A + (size_t)bm0 * DMODEL;
    const int NKT = DMODEL / BK;   // 64

    // prologue: tile 0 -> stage 0 via cp.async
    cp16(&As[0][ar0][ac0], Ab + (size_t)ar0 * DMODEL + ac0);
    cp16(&As[0][ar1][ac0], Ab + (size_t)ar1 * DMODEL + ac0);
    cp16(&Bs[0][bk0][bn4],      W + (size_t)bk0 * N + bn0 + bn4);
    cp16(&Bs[0][bk0 + 16][bn4], W + (size_t)(bk0 + 16) * N + bn0 + bn4);
    CP_COMMIT();

    int buf = 0;
    for (int kt = 0; kt < NKT; kt++) {
        if (kt + 1 < NKT) {
            int nb = buf ^ 1;
            int k0 = (kt + 1) * BK;
            cp16(&As[nb][ar0][ac0], Ab + (size_t)ar0 * DMODEL + k0 + ac0);
            cp16(&As[nb][ar1][ac0], Ab + (size_t)ar1 * DMODEL + k0 + ac0);
            cp16(&Bs[nb][bk0][bn4],      W + (size_t)(k0 + bk0) * N + bn0 + bn4);
            cp16(&Bs[nb][bk0 + 16][bn4], W + (size_t)(k0 + bk0 + 16) * N + bn0 + bn4);
            CP_COMMIT();
            CP_WAIT(1);          // tile kt arrived
        } else {
            CP_WAIT(0);
        }
        __syncthreads();

        #pragma unroll
        for (int ks = 0; ks < 4; ks++) {
            int kk = ks * 8;
            unsigned a[2][4], b[2][2];
            #pragma unroll
            for (int ms = 0; ms < 2; ms++) {
                int m = wm + ms * 16 + g;
                a[ms][0] = __float_as_uint(As[buf][m    ][kk + tg    ]);
                a[ms][1] = __float_as_uint(As[buf][m + 8][kk + tg    ]);
                a[ms][2] = __float_as_uint(As[buf][m    ][kk + tg + 4]);
                a[ms][3] = __float_as_uint(As[buf][m + 8][kk + tg + 4]);
            }
            #pragma unroll
            for (int ns = 0; ns < 2; ns++) {
                int n = wn + ns * 8 + g;
                b[ns][0] = __float_as_uint(Bs[buf][kk + tg    ][n]);
                b[ns][1] = __float_as_uint(Bs[buf][kk + tg + 4][n]);
            }
            #pragma unroll
            for (int ms = 0; ms < 2; ms++)
                #pragma unroll
                for (int ns = 0; ns < 2; ns++) {
                    asm volatile(
                        "mma.sync.aligned.m16n8k8.row.col.f32.tf32.tf32.f32 "
                        "{%0,%1,%2,%3}, {%4,%5,%6,%7}, {%8,%9}, {%0,%1,%2,%3};\n"
                        : "+f"(acc[ms][ns][0]), "+f"(acc[ms][ns][1]),
                          "+f"(acc[ms][ns][2]), "+f"(acc[ms][ns][3])
                        : "r"(a[ms][0]), "r"(a[ms][1]), "r"(a[ms][2]), "r"(a[ms][3]),
                          "r"(b[ns][0]), "r"(b[ns][1]));
                }
        }

        __syncthreads();        // next iter's cp.async will overwrite buf
        buf ^= 1;
    }

    #pragma unroll
    for (int ms = 0; ms < 2; ms++) {
        int row0 = bm0 + wm + ms * 16 + g;
        #pragma unroll
        for (int ns = 0; ns < 2; ns++) {
            int col = bn0 + wn + ns * 8 + 2 * tg;
            float b0 = bias[col], b1 = bias[col + 1];
            float o0 = acc[ms][ns][0] + b0;
            float o1 = acc[ms][ns][1] + b1;
            float o2 = acc[ms][ns][2] + b0;
            float o3 = acc[ms][ns][3] + b1;
            if (doact) { o0 = actf(o0); o1 = actf(o1); o2 = actf(o2); o3 = actf(o3); }
            float2 lo = {o0, o1}, hi = {o2, o3};
            *(float2*)(C + (size_t)row0 * N + col)       = lo;
            *(float2*)(C + (size_t)(row0 + 8) * N + col) = hi;
        }
    }
}

// ---------------------------------------------------------------------------
// K2: S[b,m,h] = sum_d aq[m,d] * ak[b,h,d]
// ---------------------------------------------------------------------------
__global__ __launch_bounds__(256) void s_kernel() {
    int b  = blockIdx.y;
    int m0 = blockIdx.x * 32;
    __shared__ float ak_s[8][132];
    __shared__ float aq_s[32][132];
    int t = threadIdx.x;
    {
        int h = t >> 5, d4 = (t & 31) * 4;
        float4 v = *(const float4*)&g_ak[b * KPROJ_N + h * DMEM + d4];
        *(float4*)&ak_s[h][d4] = v;
    }
    #pragma unroll
    for (int i = 0; i < 4; i++) {
        int idx = t + i * 256;
        int ml = idx >> 5, d4 = (idx & 31) * 4;
        float4 v = *(const float4*)&g_aq[(m0 + ml) * DMEM + d4];
        *(float4*)&aq_s[ml][d4] = v;
    }
    __syncthreads();
    int ml = t >> 3, h = t & 7;
    float s = 0.f;
    #pragma unroll
    for (int d4 = 0; d4 < 32; d4++) {
        float4 a = *(const float4*)&aq_s[ml][d4 * 4];
        float4 k = *(const float4*)&ak_s[h][d4 * 4];
        s += a.x * k.x + a.y * k.y + a.z * k.z + a.w * k.w;
    }
    g_S[(b * NM + m0 + ml) * NH + h] = s;
}

// ---------------------------------------------------------------------------
// K3: epilogue (unchanged from R9: cp.async streaming, 100us, DRAM 63.5%)
// ---------------------------------------------------------------------------
__global__ __launch_bounds__(256) void epilogue_kernel(
    const float* __restrict__ memories, const float* __restrict__ write_mass,
    const unsigned char* __restrict__ batch_mask, float* __restrict__ out)
{
    int b  = blockIdx.y;
    int m0 = blockIdx.x * 32;
    __shared__ float4 v_s[NH * 64];      // 8 KB  v[h][e4]
    __shared__ float  S_s[256];          // 1 KB  S[row*8+h]
    __shared__ float4 mem_s[32 * 32];    // 16 KB [row][d4]
    __shared__ float4 wm_s [32 * 32];    // 16 KB
    int t = threadIdx.x;
    int ml = t >> 5;
    int d4 = t & 31;
    int r0 = ml * 4;

    // si held in regs (issued first, consumed last)
    float4 si4[4];
    #pragma unroll
    for (int i = 0; i < 4; i++)
        si4[i] = *(const float4*)&g_si[(m0 + r0 + i) * DMEM + d4 * 4];
    unsigned char msk = batch_mask[b];

    // group A: v + S (needed by compute phase)
    const float4* gv = (const float4*)(g_v + (size_t)b * VPROJ_N);
    cp16(&v_s[t],       &gv[t]);
    cp16(&v_s[t + 256], &gv[t + 256]);
    cp4(&S_s[t], &g_S[((size_t)b * NM + m0) * NH + t]);
    CP_COMMIT();

    // group B: memories + write_mass (needed at tail)
    #pragma unroll
    for (int i = 0; i < 4; i++) {
        int row = r0 + i;
        size_t base = ((size_t)b * NM + m0 + row) * DMEM + d4 * 4;
        cp16(&mem_s[row * 32 + d4], &memories[base]);
        cp16(&wm_s [row * 32 + d4], &write_mass[base]);
    }
    CP_COMMIT();

    CP_WAIT(1);          // group A done
    __syncthreads();

    float4 aU[4], aL[4];
    float dn[4];
    #pragma unroll
    for (int i = 0; i < 4; i++) {
        aU[i] = make_float4(0.f, 0.f, 0.f, 0.f);
        aL[i] = make_float4(0.f, 0.f, 0.f, 0.f);
        dn[i] = 1e-5f;
    }

    #pragma unroll
    for (int h = 0; h < 8; h++) {
        float4 vu = v_s[h * 64 + d4];
        float4 vl = v_s[h * 64 + 32 + d4];
        #pragma unroll
        for (int i = 0; i < 4; i++) {
            float s = S_s[(r0 + i) * 8 + h];   // warp-uniform broadcast
            dn[i] += s;
            aU[i].x = fmaf(s, vu.x, aU[i].x); aU[i].y = fmaf(s, vu.y, aU[i].y);
            aU[i].z = fmaf(s, vu.z, aU[i].z); aU[i].w = fmaf(s, vu.w, aU[i].w);
            aL[i].x = fmaf(s, vl.x, aL[i].x); aL[i].y = fmaf(s, vl.y, aL[i].y);
            aL[i].z = fmaf(s, vl.z, aL[i].z); aL[i].w = fmaf(s, vl.w, aL[i].w);
        }
    }

    CP_WAIT(0);          // group B done
    __syncthreads();

    #pragma unroll
    for (int i = 0; i < 4; i++) {
        int row = r0 + i;
        size_t base = ((size_t)b * NM + m0 + row) * DMEM + d4 * 4;
        float4 mem = mem_s[row * 32 + d4];
        float4 wm4 = wm_s [row * 32 + d4];

        float rd = __fdividef(1.f, dn[i]);
        float4 wf;
        wf.x = 0.7f * sigm(aL[i].x * rd) * si4[i].x;
        wf.y = 0.7f * sigm(aL[i].y * rd) * si4[i].y;
        wf.z = 0.7f * sigm(aL[i].z * rd) * si4[i].z;
        wf.w = 0.7f * sigm(aL[i].w * rd) * si4[i].w;

        float4 om, oa;
        if (msk) {
            om = mem; oa = wm4;
        } else {
            om.x = mem.x + wf.x * (aU[i].x * rd - mem.x);
            om.y = mem.y + wf.y * (aU[i].y * rd - mem.y);
            om.z = mem.z + wf.z * (aU[i].z * rd - mem.z);
            om.w = mem.w + wf.w * (aU[i].w * rd - mem.w);
            oa.x = wm4.x + wf.x; oa.y = wm4.y + wf.y;
            oa.z = wm4.z + wf.z; oa.w = wm4.w + wf.w;
        }
        *(float4*)&out[base] = om;
        *(float4*)&out[MEM_ELEMS + base] = oa;
    }
}

// ---------------------------------------------------------------------------
extern "C" void kernel_launch(void* const* d_in, const int* in_sizes, int n_in,
                              void* d_out, int out_size) {
    const float* key        = (const float*)d_in[0];
    const float* values     = (const float*)d_in[1];
    const float* memories   = (const float*)d_in[2];
    const float* write_mass = (const float*)d_in[3];
    const unsigned char* batch_mask = (const unsigned char*)d_in[4];
    const float* W_key      = (const float*)d_in[5];
    const float* b_key      = (const float*)d_in[6];
    const float* W_val      = (const float*)d_in[7];
    const float* b_val      = (const float*)d_in[8];
    const float* addresses  = (const float*)d_in[9];
    const float* interp     = (const float*)d_in[10];
    float* out = (float*)d_out;

    prep_kernel<<<256, 256>>>(addresses, interp);
    proj_mma_kernel<<<dim3((KPROJ_N + VPROJ_N) / BN, NB / BM), 256>>>(
        key, values, W_key, b_key, W_val, b_val);
    s_kernel<<<dim3(NM / 32, NB), 256>>>();
    epilogue_kernel<<<dim3(NM / 32, NB), 256>>>(memories, write_mass, batch_mask, out);
}

// round 13
// speedup vs baseline: 1.7002x; 1.0304x over previous
#include <cuda_runtime.h>
#include <math.h>

#define NB 512
#define DMODEL 2048
#define NH 8
#define DMEM 128
#define NM 512
#define KPROJ_N 1024     // H*DMEM
#define VPROJ_N 2048     // 2*H*DMEM
#define MEM_ELEMS (NB*NM*DMEM)

// Scratch (device globals: no allocation allowed)
__device__ float g_ak[NB * KPROJ_N];
__device__ float g_v [NB * VPROJ_N];
__device__ float g_aq[NM * DMEM];
__device__ float g_si[NM * DMEM];
__device__ float g_S [NB * NM * NH];

__device__ __forceinline__ float actf(float x) {
    return x > 0.f ? x + 1.f : __expf(x);   // elu(x)+1
}
__device__ __forceinline__ float sigm(float x) {
    return 1.f / (1.f + __expf(-x));
}
__device__ __forceinline__ void cp16(void* s, const void* g) {
    unsigned sa = (unsigned)__cvta_generic_to_shared(s);
    asm volatile("cp.async.cg.shared.global [%0], [%1], 16;\n" :: "r"(sa), "l"(g));
}
__device__ __forceinline__ void cp4(void* s, const void* g) {
    unsigned sa = (unsigned)__cvta_generic_to_shared(s);
    asm volatile("cp.async.ca.shared.global [%0], [%1], 4;\n" :: "r"(sa), "l"(g));
}
#define CP_COMMIT() asm volatile("cp.async.commit_group;\n" ::: "memory")
#define CP_WAIT(n)  asm volatile("cp.async.wait_group %0;\n" :: "n"(n) : "memory")

// ---------------------------------------------------------------------------
// K0: aq = act(addresses), si = sigmoid(interpolation_logits)
// ---------------------------------------------------------------------------
__global__ void prep_kernel(const float* __restrict__ addresses,
                            const float* __restrict__ interp) {
    int i = blockIdx.x * blockDim.x + threadIdx.x;
    if (i < NM * DMEM) {
        g_aq[i] = actf(addresses[i]);
        g_si[i] = sigm(interp[i]);
    }
}

// ---------------------------------------------------------------------------
// K1: fused projection GEMMs via mma.sync tf32 (m16n8k8)
//   BM=64 BN=64 BK=32, 256 threads (8 warps, 2x4), warp tile 32x16.
//   3-stage cp.async pipeline, ONE __syncthreads per k-iter (R10 had two).
// ---------------------------------------------------------------------------
#define BM 64
#define BN 64
#define BK 32
#define PADA 36
#define PADB 72
#define PSTG 3

__global__ __launch_bounds__(256) void proj_mma_kernel(
    const float* __restrict__ key, const float* __restrict__ values,
    const float* __restrict__ W_key, const float* __restrict__ b_key,
    const float* __restrict__ W_val, const float* __restrict__ b_val)
{
    const float *A, *W, *bias;
    float* C;
    int N, doact;
    int bx = blockIdx.x;
    if (bx < KPROJ_N / BN) { A = key;    W = W_key; bias = b_key; C = g_ak; N = KPROJ_N; doact = 1; }
    else { bx -= KPROJ_N / BN; A = values; W = W_val; bias = b_val; C = g_v; N = VPROJ_N; doact = 0; }

    __shared__ float As[PSTG][BM][PADA];   // [stage][m][k]
    __shared__ float Bs[PSTG][BK][PADB];   // [stage][k][n]

    int t = threadIdx.x;
    int lane = t & 31;
    int warp = t >> 5;
    int g  = lane >> 2;
    int tg = lane & 3;
    int wm = (warp & 1) * 32;
    int wn = (warp >> 1) * 16;
    int bm0 = blockIdx.y * BM;
    int bn0 = bx * BN;

    float acc[2][2][4];
    #pragma unroll
    for (int i = 0; i < 2; i++)
        #pragma unroll
        for (int j = 0; j < 2; j++)
            #pragma unroll
            for (int r = 0; r < 4; r++) acc[i][j][r] = 0.f;

    int ar0 = t >> 3,        ac0 = (t & 7) * 4;     // A rows 0..31
    int ar1 = ar0 + 32;                              // A rows 32..63
    int bk0 = t >> 4,        bn4 = (t & 15) * 4;    // B k 0..15

    const float* Ab = A + (size_t)bm0 * DMODEL;
    const int NKT = DMODEL / BK;   // 64

    // prologue: stages 0..PSTG-2
    #pragma unroll
    for (int s = 0; s < PSTG - 1; s++) {
        int k0 = s * BK;
        cp16(&As[s][ar0][ac0], Ab + (size_t)ar0 * DMODEL + k0 + ac0);
        cp16(&As[s][ar1][ac0], Ab + (size_t)ar1 * DMODEL + k0 + ac0);
        cp16(&Bs[s][bk0][bn4],      W + (size_t)(k0 + bk0) * N + bn0 + bn4);
        cp16(&Bs[s][bk0 + 16][bn4], W + (size_t)(k0 + bk0 + 16) * N + bn0 + bn4);
        CP_COMMIT();
    }

    for (int kt = 0; kt < NKT; kt++) {
        CP_WAIT(PSTG - 2);       // tile kt has arrived
        __syncthreads();         // one barrier per iter: also orders the write
                                 // below into stage (kt-1)%PSTG after its compute

        int kp = kt + PSTG - 1;
        if (kp < NKT) {
            int sp = kp % PSTG;
            int k0 = kp * BK;
            cp16(&As[sp][ar0][ac0], Ab + (size_t)ar0 * DMODEL + k0 + ac0);
            cp16(&As[sp][ar1][ac0], Ab + (size_t)ar1 * DMODEL + k0 + ac0);
            cp16(&Bs[sp][bk0][bn4],      W + (size_t)(k0 + bk0) * N + bn0 + bn4);
            cp16(&Bs[sp][bk0 + 16][bn4], W + (size_t)(k0 + bk0 + 16) * N + bn0 + bn4);
        }
        CP_COMMIT();             // commit every iter (empty groups retire free)

        int buf = kt % PSTG;
        #pragma unroll
        for (int ks = 0; ks < 4; ks++) {
            int kk = ks * 8;
            unsigned a[2][4], b[2][2];
            #pragma unroll
            for (int ms = 0; ms < 2; ms++) {
                int m = wm + ms * 16 + g;
                a[ms][0] = __float_as_uint(As[buf][m    ][kk + tg    ]);
                a[ms][1] = __float_as_uint(As[buf][m + 8][kk + tg    ]);
                a[ms][2] = __float_as_uint(As[buf][m    ][kk + tg + 4]);
                a[ms][3] = __float_as_uint(As[buf][m + 8][kk + tg + 4]);
            }
            #pragma unroll
            for (int ns = 0; ns < 2; ns++) {
                int n = wn + ns * 8 + g;
                b[ns][0] = __float_as_uint(Bs[buf][kk + tg    ][n]);
                b[ns][1] = __float_as_uint(Bs[buf][kk + tg + 4][n]);
            }
            #pragma unroll
            for (int ms = 0; ms < 2; ms++)
                #pragma unroll
                for (int ns = 0; ns < 2; ns++) {
                    asm volatile(
                        "mma.sync.aligned.m16n8k8.row.col.f32.tf32.tf32.f32 "
                        "{%0,%1,%2,%3}, {%4,%5,%6,%7}, {%8,%9}, {%0,%1,%2,%3};\n"
                        : "+f"(acc[ms][ns][0]), "+f"(acc[ms][ns][1]),
                          "+f"(acc[ms][ns][2]), "+f"(acc[ms][ns][3])
                        : "r"(a[ms][0]), "r"(a[ms][1]), "r"(a[ms][2]), "r"(a[ms][3]),
                          "r"(b[ns][0]), "r"(b[ns][1]));
                }
        }
    }

    #pragma unroll
    for (int ms = 0; ms < 2; ms++) {
        int row0 = bm0 + wm + ms * 16 + g;
        #pragma unroll
        for (int ns = 0; ns < 2; ns++) {
            int col = bn0 + wn + ns * 8 + 2 * tg;
            float b0 = bias[col], b1 = bias[col + 1];
            float o0 = acc[ms][ns][0] + b0;
            float o1 = acc[ms][ns][1] + b1;
            float o2 = acc[ms][ns][2] + b0;
            float o3 = acc[ms][ns][3] + b1;
            if (doact) { o0 = actf(o0); o1 = actf(o1); o2 = actf(o2); o3 = actf(o3); }
            float2 lo = {o0, o1}, hi = {o2, o3};
            *(float2*)(C + (size_t)row0 * N + col)       = lo;
            *(float2*)(C + (size_t)(row0 + 8) * N + col) = hi;
        }
    }
}

// ---------------------------------------------------------------------------
// K2: S[b,m,h] = sum_d aq[m,d] * ak[b,h,d]
// ---------------------------------------------------------------------------
__global__ __launch_bounds__(256) void s_kernel() {
    int b  = blockIdx.y;
    int m0 = blockIdx.x * 32;
    __shared__ float ak_s[8][132];
    __shared__ float aq_s[32][132];
    int t = threadIdx.x;
    {
        int h = t >> 5, d4 = (t & 31) * 4;
        float4 v = *(const float4*)&g_ak[b * KPROJ_N + h * DMEM + d4];
        *(float4*)&ak_s[h][d4] = v;
    }
    #pragma unroll
    for (int i = 0; i < 4; i++) {
        int idx = t + i * 256;
        int ml = idx >> 5, d4 = (idx & 31) * 4;
        float4 v = *(const float4*)&g_aq[(m0 + ml) * DMEM + d4];
        *(float4*)&aq_s[ml][d4] = v;
    }
    __syncthreads();
    int ml = t >> 3, h = t & 7;
    float s = 0.f;
    #pragma unroll
    for (int d4 = 0; d4 < 32; d4++) {
        float4 a = *(const float4*)&aq_s[ml][d4 * 4];
        float4 k = *(const float4*)&ak_s[h][d4 * 4];
        s += a.x * k.x + a.y * k.y + a.z * k.z + a.w * k.w;
    }
    g_S[(b * NM + m0 + ml) * NH + h] = s;
}

// ---------------------------------------------------------------------------
// K3: epilogue. All streaming via cp.async; si moved to smem (was 16 regs);
// h-loop split into aL pass -> wf (aL dies) -> aU pass to cut peak regs;
// launch_bounds(256,3) to get 3 CTAs/SM (R10 stuck at 2, occ 23.7%).
// ---------------------------------------------------------------------------
__global__ __launch_bounds__(256, 3) void epilogue_kernel(
    const float* __restrict__ memories, const float* __restrict__ write_mass,
    const unsigned char* __restrict__ batch_mask, float* __restrict__ out)
{
    int b  = blockIdx.y;
    int m0 = blockIdx.x * 32;
    __shared__ float4 v_s[NH * 64];      // 8 KB  v[h][e4]
    __shared__ float  S_s[256];          // 1 KB  S[row*8+h]
    __shared__ float4 si_s[32 * 32];     // 16 KB [row][d4]
    __shared__ float4 mem_s[32 * 32];    // 16 KB
    __shared__ float4 wm_s [32 * 32];    // 16 KB
    int t = threadIdx.x;
    int ml = t >> 5;
    int d4 = t & 31;
    int r0 = ml * 4;

    unsigned char msk = batch_mask[b];

    // group A: v + S + si (needed by compute / wf phase)
    const float4* gv = (const float4*)(g_v + (size_t)b * VPROJ_N);
    cp16(&v_s[t],       &gv[t]);
    cp16(&v_s[t + 256], &gv[t + 256]);
    cp4(&S_s[t], &g_S[((size_t)b * NM + m0) * NH + t]);
    #pragma unroll
    for (int i = 0; i < 4; i++) {
        int row = r0 + i;
        cp16(&si_s[row * 32 + d4], &g_si[(m0 + row) * DMEM + d4 * 4]);
    }
    CP_COMMIT();

    // group B: memories + write_mass (needed only at tail)
    #pragma unroll
    for (int i = 0; i < 4; i++) {
        int row = r0 + i;
        size_t base = ((size_t)b * NM + m0 + row) * DMEM + d4 * 4;
        cp16(&mem_s[row * 32 + d4], &memories[base]);
        cp16(&wm_s [row * 32 + d4], &write_mass[base]);
    }
    CP_COMMIT();

    CP_WAIT(1);          // group A done
    __syncthreads();

    float dn[4] = {1e-5f, 1e-5f, 1e-5f, 1e-5f};

    // pass 1: write-logit accumulation (reads only lower half of v)
    float4 aL[4];
    #pragma unroll
    for (int i = 0; i < 4; i++) aL[i] = make_float4(0.f, 0.f, 0.f, 0.f);
    #pragma unroll
    for (int h = 0; h < 8; h++) {
        float4 vl = v_s[h * 64 + 32 + d4];
        #pragma unroll
        for (int i = 0; i < 4; i++) {
            float s = S_s[(r0 + i) * 8 + h];
            dn[i] += s;
            aL[i].x = fmaf(s, vl.x, aL[i].x); aL[i].y = fmaf(s, vl.y, aL[i].y);
            aL[i].z = fmaf(s, vl.z, aL[i].z); aL[i].w = fmaf(s, vl.w, aL[i].w);
        }
    }

    // wf (aL registers die here)
    float rdv[4];
    float4 wf[4];
    #pragma unroll
    for (int i = 0; i < 4; i++) {
        rdv[i] = __fdividef(1.f, dn[i]);
        float4 si = si_s[(r0 + i) * 32 + d4];
        wf[i].x = 0.7f * sigm(aL[i].x * rdv[i]) * si.x;
        wf[i].y = 0.7f * sigm(aL[i].y * rdv[i]) * si.y;
        wf[i].z = 0.7f * sigm(aL[i].z * rdv[i]) * si.z;
        wf[i].w = 0.7f * sigm(aL[i].w * rdv[i]) * si.w;
    }

    // pass 2: update accumulation (reads only upper half of v)
    float4 aU[4];
    #pragma unroll
    for (int i = 0; i < 4; i++) aU[i] = make_float4(0.f, 0.f, 0.f, 0.f);
    #pragma unroll
    for (int h = 0; h < 8; h++) {
        float4 vu = v_s[h * 64 + d4];
        #pragma unroll
        for (int i = 0; i < 4; i++) {
            float s = S_s[(r0 + i) * 8 + h];
            aU[i].x = fmaf(s, vu.x, aU[i].x); aU[i].y = fmaf(s, vu.y, aU[i].y);
            aU[i].z = fmaf(s, vu.z, aU[i].z); aU[i].w = fmaf(s, vu.w, aU[i].w);
        }
    }

    CP_WAIT(0);          // group B done
    __syncthreads();

    #pragma unroll
    for (int i = 0; i < 4; i++) {
        int row = r0 + i;
        size_t base = ((size_t)b * NM + m0 + row) * DMEM + d4 * 4;
        float4 mem = mem_s[row * 32 + d4];
        float4 wm4 = wm_s [row * 32 + d4];

        float4 om, oa;
        if (msk) {
            om = mem; oa = wm4;
        } else {
            om.x = mem.x + wf[i].x * (aU[i].x * rdv[i] - mem.x);
            om.y = mem.y + wf[i].y * (aU[i].y * rdv[i] - mem.y);
            om.z = mem.z + wf[i].z * (aU[i].z * rdv[i] - mem.z);
            om.w = mem.w + wf[i].w * (aU[i].w * rdv[i] - mem.w);
            oa.x = wm4.x + wf[i].x; oa.y = wm4.y + wf[i].y;
            oa.z = wm4.z + wf[i].z; oa.w = wm4.w + wf[i].w;
        }
        *(float4*)&out[base] = om;
        *(float4*)&out[MEM_ELEMS + base] = oa;
    }
}

// ---------------------------------------------------------------------------
extern "C" void kernel_launch(void* const* d_in, const int* in_sizes, int n_in,
                              void* d_out, int out_size) {
    const float* key        = (const float*)d_in[0];
    const float* values     = (const float*)d_in[1];
    const float* memories   = (const float*)d_in[2];
    const float* write_mass = (const float*)d_in[3];
    const unsigned char* batch_mask = (const unsigned char*)d_in[4];
    const float* W_key      = (const float*)d_in[5];
    const float* b_key      = (const float*)d_in[6];
    const float* W_val      = (const float*)d_in[7];
    const float* b_val      = (const float*)d_in[8];
    const float* addresses  = (const float*)d_in[9];
    const float* interp     = (const float*)d_in[10];
    float* out = (float*)d_out;

    prep_kernel<<<256, 256>>>(addresses, interp);
    proj_mma_kernel<<<dim3((KPROJ_N + VPROJ_N) / BN, NB / BM), 256>>>(
        key, values, W_key, b_key, W_val, b_val);
    s_kernel<<<dim3(NM / 32, NB), 256>>>();
    epilogue_kernel<<<dim3(NM / 32, NB), 256>>>(memories, write_mass, batch_mask, out);
}